// round 17
// baseline (speedup 1.0000x reference)
#include <cuda_runtime.h>
#include <cuda_bf16.h>
#include <cstdint>
#include <math.h>

#define DD     5
#define HGRID  24
#define WGRID  48
#define CLV    1024
#define NB     4
#define DIM    128
#define LMAX   12
#define DEPTH  6
#define LTOK   16
#define BALL   (DD*HGRID*WGRID)   // 5760
#define NROW   (BALL*LTOK)        // 92160
#define CAP    64
#define HID    512
#define AS     72                 // smem row stride in bf16 (144B: conflict-free ldmatrix)
#define PANEL  18432              // bytes per 128x64 panel
#define PANELW 9216               // bf16 elems per panel

typedef __nv_bfloat16 bf16;

// ---------------- device scratch ----------------
__device__ int   g_counts[BALL];
__device__ int   g_list[BALL*CAP];
__device__ int   g_sel[BALL*LMAX];
__device__ int   g_m[BALL];
__device__ float g_bgp[NB*DIM];
__device__ float g_h[NROW*DIM];
__device__ bf16  g_qkvb[NROW*3*DIM];              // bf16 QKV
__device__ bf16  g_a1[NROW*DIM],  g_a2[NROW*DIM]; // layer-0 LN split only
__device__ bf16  g_h1a[NROW*HID];                 // single-bf16 gelu(h1)
__device__ bf16  g_fa1[BALL*HID], g_fa2[BALL*HID];
// transposed + split weights: [n][k] k-fast
__device__ bf16  g_wqkvT1[DEPTH*3*DIM*DIM], g_wqkvT2[DEPTH*3*DIM*DIM];
__device__ bf16  g_woT1[DEPTH*DIM*DIM],     g_woT2[DEPTH*DIM*DIM];
__device__ bf16  g_w1T1[DEPTH*HID*DIM],     g_w1T2[DEPTH*HID*DIM];
__device__ bf16  g_w2T1[DEPTH*DIM*HID],     g_w2T2[DEPTH*DIM*HID];
__device__ bf16  g_pT1[CLV*HID],            g_pT2[CLV*HID];

// ---------------- helpers ----------------
__device__ __forceinline__ uint32_t s2u(const void* p){
    uint32_t a;
    asm("{ .reg .u64 t; cvta.to.shared.u64 t, %1; cvt.u32.u64 %0, t; }" : "=r"(a) : "l"(p));
    return a;
}
__device__ __forceinline__ void cp16(uint32_t dst, const void* src){
    asm volatile("cp.async.cg.shared.global [%0], [%1], 16;" :: "r"(dst), "l"(src));
}
#define CPCOMMIT() asm volatile("cp.async.commit_group;" ::: "memory")
#define CPWAIT0()  asm volatile("cp.async.wait_group 0;" ::: "memory")
__device__ __forceinline__ void ldsm_x4(uint32_t* d, uint32_t addr){
    asm volatile("ldmatrix.sync.aligned.m8n8.x4.shared.b16 {%0,%1,%2,%3}, [%4];"
        : "=r"(d[0]),"=r"(d[1]),"=r"(d[2]),"=r"(d[3]) : "r"(addr));
}
__device__ __forceinline__ void ldsm_x2(uint32_t* d, uint32_t addr){
    asm volatile("ldmatrix.sync.aligned.m8n8.x2.shared.b16 {%0,%1}, [%2];"
        : "=r"(d[0]),"=r"(d[1]) : "r"(addr));
}
__device__ __forceinline__ void mma16816(float* c, const uint32_t* a, const uint32_t* b){
    asm volatile("mma.sync.aligned.m16n8k16.row.col.f32.bf16.bf16.f32 "
        "{%0,%1,%2,%3}, {%4,%5,%6,%7}, {%8,%9}, {%0,%1,%2,%3};"
        : "+f"(c[0]),"+f"(c[1]),"+f"(c[2]),"+f"(c[3])
        : "r"(a[0]),"r"(a[1]),"r"(a[2]),"r"(a[3]), "r"(b[0]),"r"(b[1]));
}
__device__ __forceinline__ float gelu_f(float x){
    float x3 = x*x*x;
    return 0.5f*x*(1.0f + tanhf(0.7978845608028654f*(x + 0.044715f*x3)));
}
__device__ __forceinline__ void split1(float v, bf16 &h, bf16 &l){
    h = __float2bfloat16(v);
    l = __float2bfloat16(v - __bfloat162float(h));
}
__device__ __forceinline__ float4 ld4bf(const bf16* p){
    uint2 r = *(const uint2*)p;
    __nv_bfloat162 a = *(__nv_bfloat162*)&r.x;
    __nv_bfloat162 b = *(__nv_bfloat162*)&r.y;
    return make_float4(__bfloat162float(a.x), __bfloat162float(a.y),
                       __bfloat162float(b.x), __bfloat162float(b.y));
}

#define GF_ACCUM   1
#define GF_GELU    2
#define GF_SPLIT   4
#define GF_MASK    8
#define GF_LN      16
#define GF_B16     32
#define GF_SMEMOUT 64

// ---------------- setup kernels ----------------
__global__ void k_zero(){
    int i = blockIdx.x*blockDim.x + threadIdx.x;
    if (i < BALL) g_counts[i] = 0;
}
__global__ void k_scatter(const int* __restrict__ li, int n){
    int i = blockIdx.x*blockDim.x + threadIdx.x;
    if (i >= n) return;
    int flat = li[3*i]*(HGRID*WGRID) + li[3*i+1]*WGRID + li[3*i+2];
    int slot = atomicAdd(&g_counts[flat], 1);
    if (slot < CAP) g_list[flat*CAP + slot] = i;
}
__global__ void k_bg(const float* __restrict__ ob, const float* __restrict__ dw,
                     const float* __restrict__ db){
    int c = blockIdx.x*blockDim.x + threadIdx.x;
    if (c >= NB*DIM) return;
    float s = 0.0f;
    for (int m = 0; m < NB; m++){
        const float* bg = ob + m*DIM;
        float t = 0.0f;
        for (int k = 0; k < DIM; k++) t += bg[k] * dw[k*(NB*DIM) + c];
        s += t;
    }
    g_bgp[c] = ob[c] + s*(1.0f/NB) + db[c];
}
__global__ void k_select(){
    int cell = blockIdx.x*blockDim.x + threadIdx.x;
    if (cell >= BALL) return;
    int cnt = g_counts[cell];
    int avail = min(cnt, CAP);
    int m = min(cnt, LMAX);
    g_m[cell] = m;
    if (cnt <= LMAX){
        for (int j = 0; j < m; j++) g_sel[cell*LMAX + j] = g_list[cell*CAP + j];
    } else {
        int tmp[CAP];
        for (int j = 0; j < avail; j++) tmp[j] = g_list[cell*CAP + j];
        for (int a = 0; a < m; a++){
            int best = a;
            for (int b = a+1; b < avail; b++) if (tmp[b] < tmp[best]) best = b;
            int t = tmp[best]; tmp[best] = tmp[a]; tmp[a] = t;
            g_sel[cell*LMAX + a] = t;
        }
    }
}
__global__ void k_assemble(const float* __restrict__ x){
    int idx = blockIdx.x*blockDim.x + threadIdx.x;
    if (idx >= NROW*DIM) return;
    int row = idx >> 7, d = idx & 127;
    int cell = row >> 4, lr = row & 15;
    float v;
    if (lr < NB) v = g_bgp[lr*DIM + d];
    else {
        int j = lr - NB;
        v = (j < g_m[cell]) ? x[(size_t)g_sel[cell*LMAX + j]*DIM + d] : 0.0f;
    }
    g_h[idx] = v;
}
__global__ void k_tsplit(const float* __restrict__ W, bf16* __restrict__ T1,
                         bf16* __restrict__ T2, int K, int N){
    size_t off = (size_t)blockIdx.y * K * N;
    W += off; T1 += off; T2 += off;
    int tot = K*N;
    for (int idx = blockIdx.x*blockDim.x + threadIdx.x; idx < tot;
         idx += gridDim.x*blockDim.x){
        int n = idx / K, k = idx - n*K;
        float v = W[(size_t)k*N + n];
        bf16 h, l; split1(v, h, l);
        T1[idx] = h; T2[idx] = l;
    }
}
// LayerNorm + bf16 split (layer 0 only)
__global__ void k_ln_split(const float* __restrict__ w, const float* __restrict__ b){
    int warp = threadIdx.x >> 5, lane = threadIdx.x & 31;
    int row = blockIdx.x*8 + warp;
    const float* src = g_h + (size_t)row*DIM;
    float4 v = *(const float4*)(src + lane*4);
    float s  = v.x+v.y+v.z+v.w;
    float ss = v.x*v.x+v.y*v.y+v.z*v.z+v.w*v.w;
    #pragma unroll
    for (int o = 16; o; o >>= 1){
        s  += __shfl_xor_sync(0xffffffffu, s,  o);
        ss += __shfl_xor_sync(0xffffffffu, ss, o);
    }
    float mean = s*(1.0f/DIM);
    float var  = ss*(1.0f/DIM) - mean*mean;
    float rstd = rsqrtf(var + 1e-5f);
    float4 wv = *(const float4*)(w + lane*4);
    float4 bv = *(const float4*)(b + lane*4);
    float n0 = (v.x-mean)*rstd*wv.x + bv.x;
    float n1 = (v.y-mean)*rstd*wv.y + bv.y;
    float n2 = (v.z-mean)*rstd*wv.z + bv.z;
    float n3 = (v.w-mean)*rstd*wv.w + bv.w;
    bf16 h0,l0,h1,l1,h2,l2,h3,l3;
    split1(n0,h0,l0); split1(n1,h1,l1); split1(n2,h2,l2); split1(n3,h3,l3);
    __nv_bfloat162* d1 = (__nv_bfloat162*)(g_a1 + (size_t)row*DIM + lane*4);
    __nv_bfloat162* d2 = (__nv_bfloat162*)(g_a2 + (size_t)row*DIM + lane*4);
    __nv_bfloat162 p;
    p.x=h0; p.y=h1; d1[0]=p;  p.x=h2; p.y=h3; d1[1]=p;
    p.x=l0; p.y=l1; d2[0]=p;  p.x=l2; p.y=l3; d2[1]=p;
}
__global__ void k_split_feat(){
    int idx = blockIdx.x*blockDim.x + threadIdx.x;
    if (idx >= BALL*HID) return;
    int cell = idx >> 9, k = idx & 511;
    float v = g_h[(size_t)cell*(LTOK*DIM) + k];
    bf16 h, l; split1(v, h, l);
    g_fa1[idx] = h; g_fa2[idx] = l;
}

// ---------------- shared MMA chunk over one 64-k slab in smem ----------------
template<bool A2ON>
__device__ __forceinline__ void chunk_mma(float (&acc)[2][8][4],
                                          uint32_t abase, uint32_t bbase){
    #pragma unroll
    for (int k16 = 0; k16 < 64; k16 += 16){
        uint32_t a1f[2][4], a2f[2][4];
        #pragma unroll
        for (int mt = 0; mt < 2; mt++){
            uint32_t ad = abase + (uint32_t)((mt*16*AS + k16) * 2);
            ldsm_x4(a1f[mt], ad);
            if (A2ON) ldsm_x4(a2f[mt], ad + PANEL);
        }
        #pragma unroll
        for (int nt = 0; nt < 8; nt++){
            uint32_t bd = bbase + (uint32_t)((nt*8*AS + k16) * 2);
            uint32_t b1f[2], b2f[2];
            ldsm_x2(b1f, bd);
            ldsm_x2(b2f, bd + PANEL);
            mma16816(acc[0][nt], a1f[0], b1f);
            mma16816(acc[1][nt], a1f[1], b1f);
            if (A2ON){
                mma16816(acc[0][nt], a2f[0], b1f);
                mma16816(acc[1][nt], a2f[1], b1f);
            }
            mma16816(acc[0][nt], a1f[0], b2f);
            mma16816(acc[1][nt], a1f[1], b2f);
        }
    }
}

// ---------------- shared epilogue ----------------
__device__ __forceinline__ void gemm_epilogue(
    float (&acc)[2][8][4], int row0, int cofs,
    const float* __restrict__ bias,
    float* __restrict__ Cout, int ldc,
    bf16* __restrict__ O1, bf16* __restrict__ O2, int ldo,
    const float* __restrict__ lnw, const float* __restrict__ lnb,
    float2* red, int flags, int lane, int warpM, int warpN,
    bf16* smem_bf)
{
    const int l4 = lane >> 2, l2 = (lane & 3) << 1;

    if (flags & GF_LN){
        #pragma unroll
        for (int mt = 0; mt < 2; mt++){
            #pragma unroll
            for (int hh = 0; hh < 2; hh++){
                int rl = warpM*32 + mt*16 + hh*8 + l4;
                int rg = row0 + rl;
                float s = 0.0f, ss = 0.0f;
                #pragma unroll
                for (int nt = 0; nt < 8; nt++){
                    int cg = warpN*64 + nt*8 + l2;
                    float2 old = *(const float2*)(Cout + (size_t)rg*ldc + cg);
                    float v0 = acc[mt][nt][hh*2+0] + bias[cg]   + old.x;
                    float v1 = acc[mt][nt][hh*2+1] + bias[cg+1] + old.y;
                    acc[mt][nt][hh*2+0] = v0;
                    acc[mt][nt][hh*2+1] = v1;
                    *(float2*)(Cout + (size_t)rg*ldc + cg) = make_float2(v0, v1);
                    s += v0 + v1; ss += v0*v0 + v1*v1;
                }
                s  += __shfl_xor_sync(0xffffffffu, s,  1);
                ss += __shfl_xor_sync(0xffffffffu, ss, 1);
                s  += __shfl_xor_sync(0xffffffffu, s,  2);
                ss += __shfl_xor_sync(0xffffffffu, ss, 2);
                if ((lane & 3) == 0) red[rl*2 + warpN] = make_float2(s, ss);
            }
        }
        __syncthreads();
        #pragma unroll
        for (int mt = 0; mt < 2; mt++){
            #pragma unroll
            for (int hh = 0; hh < 2; hh++){
                int rl = warpM*32 + mt*16 + hh*8 + l4;
                int rg = row0 + rl;
                float2 r0 = red[rl*2 + 0], r1 = red[rl*2 + 1];
                float mean = (r0.x + r1.x) * (1.0f/DIM);
                float var  = (r0.y + r1.y) * (1.0f/DIM) - mean*mean;
                float rstd = rsqrtf(var + 1e-5f);
                #pragma unroll
                for (int nt = 0; nt < 8; nt++){
                    int cg = warpN*64 + nt*8 + l2;
                    float n0 = (acc[mt][nt][hh*2+0] - mean)*rstd*lnw[cg]   + lnb[cg];
                    float n1 = (acc[mt][nt][hh*2+1] - mean)*rstd*lnw[cg+1] + lnb[cg+1];
                    bf16 ha,la,hb,lb;
                    split1(n0, ha, la); split1(n1, hb, lb);
                    __nv_bfloat162 p, q;
                    p.x=ha; p.y=hb; q.x=la; q.y=lb;
                    if (flags & GF_SMEMOUT){
                        int p0 = (cg >> 6) * 2;
                        int c63 = cg & 63;
                        *(__nv_bfloat162*)(smem_bf + p0*PANELW     + rl*AS + c63) = p;
                        *(__nv_bfloat162*)(smem_bf + (p0+1)*PANELW + rl*AS + c63) = q;
                    } else {
                        *(__nv_bfloat162*)(O1 + (size_t)rg*ldo + cg) = p;
                        *(__nv_bfloat162*)(O2 + (size_t)rg*ldo + cg) = q;
                    }
                }
            }
        }
        return;
    }

    #pragma unroll
    for (int mt = 0; mt < 2; mt++){
        #pragma unroll
        for (int hh = 0; hh < 2; hh++){
            int rg = row0 + warpM*32 + mt*16 + l4 + hh*8;
            bool maskz = (flags & GF_MASK) && (g_counts[rg] == 0);
            #pragma unroll
            for (int nt = 0; nt < 8; nt++){
                int cg = cofs + warpN*64 + nt*8 + l2;
                float v0 = acc[mt][nt][hh*2+0] + bias[cg];
                float v1 = acc[mt][nt][hh*2+1] + bias[cg+1];
                if (flags & GF_GELU){ v0 = gelu_f(v0); v1 = gelu_f(v1); }
                if (flags & GF_ACCUM){
                    float2 old = *(const float2*)(Cout + (size_t)rg*ldc + cg);
                    v0 += old.x; v1 += old.y;
                }
                if (flags & GF_SPLIT){
                    bf16 ha,la,hb,lb;
                    split1(v0, ha, la); split1(v1, hb, lb);
                    __nv_bfloat162 p;
                    p.x=ha; p.y=hb; *(__nv_bfloat162*)(O1 + (size_t)rg*ldo + cg) = p;
                    p.x=la; p.y=lb; *(__nv_bfloat162*)(O2 + (size_t)rg*ldo + cg) = p;
                } else if (flags & GF_B16){
                    __nv_bfloat162 p;
                    p.x = __float2bfloat16(v0); p.y = __float2bfloat16(v1);
                    *(__nv_bfloat162*)(O1 + (size_t)rg*ldo + cg) = p;
                } else {
                    float2 ov = maskz ? make_float2(0.f, 0.f) : make_float2(v0, v1);
                    *(float2*)(Cout + (size_t)rg*ldc + cg) = ov;
                }
            }
        }
    }
}

// ---------------- standalone mma.sync GEMM (L0 qkv, final w2, proj) ----------------
template<bool ARES, bool A2ON>
__global__ __launch_bounds__(256, 2)
void k_gemm(const bf16* __restrict__ A1, const bf16* __restrict__ A2, int lda,
            const bf16* __restrict__ B1, const bf16* __restrict__ B2,
            const float* __restrict__ bias,
            float* __restrict__ Cout, int ldc,
            bf16* __restrict__ O1, bf16* __restrict__ O2, int ldo,
            const float* __restrict__ lnw, const float* __restrict__ lnb,
            int Ktot, int ny, int flags){
    extern __shared__ bf16 smem[];
    const int tid = threadIdx.x, lane = tid & 31, wid = tid >> 5;
    const int warpM = wid & 3, warpN = wid >> 2;
    const int row0 = blockIdx.x*128;
    const uint32_t sbase = s2u(smem);
    const uint32_t BBASE = ARES ? 4*PANEL : 2*PANEL;
    float2* red = (float2*)((char*)smem + (ARES ? 6*PANEL : 4*PANEL));

    const int rowA = lane & 15, kA8 = (lane >> 4) << 3;
    const int rowB = lane & 7,  kB8 = ((lane >> 3) & 1) << 3;
    const uint32_t aoff0 = (uint32_t)(((warpM*32 + rowA)*AS + kA8) * 2);
    const uint32_t boff  = sbase + BBASE + (uint32_t)(((warpN*64 + rowB)*AS + kB8) * 2);

    float acc[2][8][4];

    if (ARES){
        #pragma unroll
        for (int p = 0; p < 4; p++){
            int chunk = p >> 1;
            const bf16* src = (p & 1) ? A2 : A1;
            #pragma unroll
            for (int it = 0; it < 4; it++){
                int idx = it*256 + tid;
                int r = idx >> 3, c8 = (idx & 7) << 3;
                cp16(sbase + p*PANEL + (uint32_t)((r*AS + c8)*2),
                     src + (size_t)(row0+r)*lda + chunk*64 + c8);
            }
        }
        CPCOMMIT();

        for (int nb = 0; nb < ny; nb++){
            int cofs = nb*128;
            #pragma unroll
            for (int mt = 0; mt < 2; mt++)
                #pragma unroll
                for (int nt = 0; nt < 8; nt++)
                    #pragma unroll
                    for (int q = 0; q < 4; q++) acc[mt][nt][q] = 0.0f;

            for (int kc2 = 0; kc2 < 2; kc2++){
                #pragma unroll
                for (int it = 0; it < 4; it++){
                    int idx = it*256 + tid;
                    int r = idx >> 3, c8 = (idx & 7) << 3;
                    uint32_t so = (uint32_t)((r*AS + c8)*2);
                    cp16(sbase + BBASE + so,         B1 + (size_t)(cofs+r)*Ktot + kc2*64 + c8);
                    cp16(sbase + BBASE + PANEL + so, B2 + (size_t)(cofs+r)*Ktot + kc2*64 + c8);
                }
                CPCOMMIT();
                CPWAIT0();
                __syncthreads();
                chunk_mma<true>(acc, sbase + (uint32_t)(kc2*2*PANEL) + aoff0, boff);
                __syncthreads();
            }
            gemm_epilogue(acc, row0, cofs, bias, Cout, ldc, O1, O2, ldo,
                          lnw, lnb, red, flags, lane, warpM, warpN, smem);
            __syncthreads();
        }
    } else {
        const int cofs = blockIdx.y*128;
        #pragma unroll
        for (int mt = 0; mt < 2; mt++)
            #pragma unroll
            for (int nt = 0; nt < 8; nt++)
                #pragma unroll
                for (int q = 0; q < 4; q++) acc[mt][nt][q] = 0.0f;

        for (int kc = 0; kc < Ktot; kc += 64){
            #pragma unroll
            for (int it = 0; it < 4; it++){
                int idx = it*256 + tid;
                int r = idx >> 3, c8 = (idx & 7) << 3;
                uint32_t so = (uint32_t)((r*AS + c8)*2);
                cp16(sbase + so, A1 + (size_t)(row0+r)*lda + kc + c8);
                if (A2ON) cp16(sbase + PANEL + so, A2 + (size_t)(row0+r)*lda + kc + c8);
                cp16(sbase + 2*PANEL + so, B1 + (size_t)(cofs+r)*Ktot + kc + c8);
                cp16(sbase + 3*PANEL + so, B2 + (size_t)(cofs+r)*Ktot + kc + c8);
            }
            CPCOMMIT();
            CPWAIT0();
            __syncthreads();
            chunk_mma<A2ON>(acc, sbase + aoff0, boff);
            __syncthreads();
        }
        gemm_epilogue(acc, row0, cofs, bias, Cout, ldc, O1, O2, ldo,
                      lnw, lnb, red, flags, lane, warpM, warpN, smem);
    }
}

// ---------------- fused kernel: streaming GEMM + LN -> smem + A-resident GEMM -----
template<int KW, bool A2W, int NY2>
__global__ __launch_bounds__(256, 2)
void k_fused(const bf16* __restrict__ A1, const bf16* __restrict__ A2, int lda,
             const bf16* __restrict__ Bw1, const bf16* __restrict__ Bw2,
             const float* __restrict__ biasW,
             float* __restrict__ hres,
             const float* __restrict__ lnw, const float* __restrict__ lnb,
             const bf16* __restrict__ B21, const bf16* __restrict__ B22,
             const float* __restrict__ bias2,
             float* __restrict__ C2, int ldc2,
             bf16* __restrict__ O2b, int ldo2,
             int flags2){
    extern __shared__ bf16 smem[];
    const int tid = threadIdx.x, lane = tid & 31, wid = tid >> 5;
    const int warpM = wid & 3, warpN = wid >> 2;
    const int row0 = blockIdx.x*128;
    const uint32_t sbase = s2u(smem);
    float2* red = (float2*)((char*)smem + 6*PANEL);

    const int rowA = lane & 15, kA8 = (lane >> 4) << 3;
    const int rowB = lane & 7,  kB8 = ((lane >> 3) & 1) << 3;
    const uint32_t aoff0 = (uint32_t)(((warpM*32 + rowA)*AS + kA8) * 2);
    const uint32_t boffB = sbase + 4*PANEL + (uint32_t)(((warpN*64 + rowB)*AS + kB8) * 2);

    float acc[2][8][4];

    // ---- phase 1 ----
    #pragma unroll
    for (int mt = 0; mt < 2; mt++)
        #pragma unroll
        for (int nt = 0; nt < 8; nt++)
            #pragma unroll
            for (int q = 0; q < 4; q++) acc[mt][nt][q] = 0.0f;

    for (int kc = 0; kc < KW; kc += 64){
        #pragma unroll
        for (int it = 0; it < 4; it++){
            int idx = it*256 + tid;
            int r = idx >> 3, c8 = (idx & 7) << 3;
            uint32_t so = (uint32_t)((r*AS + c8)*2);
            cp16(sbase + so, A1 + (size_t)(row0+r)*lda + kc + c8);
            if (A2W) cp16(sbase + PANEL + so, A2 + (size_t)(row0+r)*lda + kc + c8);
            cp16(sbase + 4*PANEL + so, Bw1 + (size_t)r*KW + kc + c8);
            cp16(sbase + 5*PANEL + so, Bw2 + (size_t)r*KW + kc + c8);
        }
        CPCOMMIT();
        CPWAIT0();
        __syncthreads();
        chunk_mma<A2W>(acc, sbase + aoff0, boffB);
        __syncthreads();
    }
    gemm_epilogue(acc, row0, 0, biasW, hres, DIM, (bf16*)0, (bf16*)0, 0,
                  lnw, lnb, red, GF_ACCUM|GF_LN|GF_SMEMOUT, lane, warpM, warpN, smem);
    __syncthreads();

    // ---- phase 2 ----
    for (int nb = 0; nb < NY2; nb++){
        int cofs = nb*128;
        #pragma unroll
        for (int mt = 0; mt < 2; mt++)
            #pragma unroll
            for (int nt = 0; nt < 8; nt++)
                #pragma unroll
                for (int q = 0; q < 4; q++) acc[mt][nt][q] = 0.0f;

        for (int kc2 = 0; kc2 < 2; kc2++){
            #pragma unroll
            for (int it = 0; it < 4; it++){
                int idx = it*256 + tid;
                int r = idx >> 3, c8 = (idx & 7) << 3;
                uint32_t so = (uint32_t)((r*AS + c8)*2);
                cp16(sbase + 4*PANEL + so, B21 + (size_t)(cofs+r)*DIM + kc2*64 + c8);
                cp16(sbase + 5*PANEL + so, B22 + (size_t)(cofs+r)*DIM + kc2*64 + c8);
            }
            CPCOMMIT();
            CPWAIT0();
            __syncthreads();
            chunk_mma<true>(acc, sbase + (uint32_t)(kc2*2*PANEL) + aoff0, boffB);
            __syncthreads();
        }
        gemm_epilogue(acc, row0, cofs, bias2, C2, ldc2, O2b, (bf16*)0, ldo2,
                      (float*)0, (float*)0, red, flags2, lane, warpM, warpN, smem);
        __syncthreads();
    }
}

// ---------------- attention-fused kernel: attn -> smem A + wo+LN -> smem + w1 ----
// Each CTA owns 128 rows = 8 cells; warp w handles cell row0/16 + w.
// Attention streams K and V exactly once: Q register-resident, scores staged in
// the (free) B-panel smem region, per-head softmax, then V pass accumulates O.
__global__ __launch_bounds__(256, 2)
void k_afused(const bf16* __restrict__ qkvb,
              const bf16* __restrict__ Bw1, const bf16* __restrict__ Bw2,
              const float* __restrict__ biasW,
              float* __restrict__ hres,
              const float* __restrict__ lnw, const float* __restrict__ lnb,
              const bf16* __restrict__ B21, const bf16* __restrict__ B22,
              const float* __restrict__ bias2,
              bf16* __restrict__ O2b, int ldo2, int flags2){
    extern __shared__ bf16 smem[];
    const int tid = threadIdx.x, lane = tid & 31, wid = tid >> 5;
    const int warpM = wid & 3, warpN = wid >> 2;
    const int row0 = blockIdx.x*128;
    const uint32_t sbase = s2u(smem);
    float2* red = (float2*)((char*)smem + 6*PANEL);

    const int rowA = lane & 15, kA8 = (lane >> 4) << 3;
    const int rowB = lane & 7,  kB8 = ((lane >> 3) & 1) << 3;
    const uint32_t aoff0 = (uint32_t)(((warpM*32 + rowA)*AS + kA8) * 2);
    const uint32_t boffB = sbase + 4*PANEL + (uint32_t)(((warpN*64 + rowB)*AS + kB8) * 2);

    // ---- attention prologue ----
    {
        const int qoff = ((lane >> 3) << 5) + ((lane & 7) << 2);
        const int head = lane >> 3;
        const float scale = 0.17677669529663687f;
        const size_t base = (size_t)(row0 + wid*LTOK);
        const int p0 = (qoff >> 6) * 2;
        const int c63 = qoff & 63;
        // per (warp, head) score tile in free B-panel region: 8*4*256 floats = 32 KB
        float* sc_s = (float*)((char*)smem + 4*PANEL) + (wid*4 + head)*(LTOK*LTOK);

        // pass 1: Q resident, stream K once, scores -> smem
        float4 q[LTOK];
        #pragma unroll
        for (int r = 0; r < LTOK; r++)
            q[r] = ld4bf(qkvb + (base+r)*384 + qoff);
        #pragma unroll 4
        for (int j = 0; j < LTOK; j++){
            float4 k4 = ld4bf(qkvb + (base+j)*384 + 128 + qoff);
            #pragma unroll
            for (int r = 0; r < LTOK; r++){
                float sd = q[r].x*k4.x + q[r].y*k4.y + q[r].z*k4.z + q[r].w*k4.w;
                sd += __shfl_xor_sync(0xffffffffu, sd, 1);
                sd += __shfl_xor_sync(0xffffffffu, sd, 2);
                sd += __shfl_xor_sync(0xffffffffu, sd, 4);
                if ((lane & 7) == 0) sc_s[r*LTOK + j] = sd * scale;
            }
        }
        __syncwarp();

        // pass 2: softmax rows in smem (all lanes of the head group redundant)
        #pragma unroll
        for (int r = 0; r < LTOK; r++){
            float mx = -1e30f;
            #pragma unroll
            for (int j = 0; j < LTOK; j++) mx = fmaxf(mx, sc_s[r*LTOK + j]);
            float p[LTOK]; float den = 0.0f;
            #pragma unroll
            for (int j = 0; j < LTOK; j++){ p[j] = __expf(sc_s[r*LTOK + j] - mx); den += p[j]; }
            float inv = __fdividef(1.0f, den);
            if ((lane & 7) == 0){
                #pragma unroll
                for (int j = 0; j < LTOK; j++) sc_s[r*LTOK + j] = p[j]*inv;
            }
        }
        __syncwarp();

        // pass 3: stream V once, accumulate all O rows
        float4 o[LTOK];
        #pragma unroll
        for (int r = 0; r < LTOK; r++) o[r] = make_float4(0.f,0.f,0.f,0.f);
        #pragma unroll 4
        for (int j = 0; j < LTOK; j++){
            float4 v4 = ld4bf(qkvb + (base+j)*384 + 256 + qoff);
            #pragma unroll
            for (int r = 0; r < LTOK; r++){
                float p = sc_s[r*LTOK + j];
                o[r].x += p*v4.x; o[r].y += p*v4.y; o[r].z += p*v4.z; o[r].w += p*v4.w;
            }
        }
        // write split-bf16 O into A panels
        #pragma unroll
        for (int r = 0; r < LTOK; r++){
            bf16 h0,l0,h1,l1,h2,l2,h3,l3;
            split1(o[r].x,h0,l0); split1(o[r].y,h1,l1);
            split1(o[r].z,h2,l2); split1(o[r].w,h3,l3);
            const int rl = wid*LTOK + r;
            __nv_bfloat162 pq, qq;
            pq.x=h0; pq.y=h1; qq.x=l0; qq.y=l1;
            *(__nv_bfloat162*)(smem + p0*PANELW     + rl*AS + c63)     = pq;
            *(__nv_bfloat162*)(smem + (p0+1)*PANELW + rl*AS + c63)     = qq;
            pq.x=h2; pq.y=h3; qq.x=l2; qq.y=l3;
            *(__nv_bfloat162*)(smem + p0*PANELW     + rl*AS + c63 + 2) = pq;
            *(__nv_bfloat162*)(smem + (p0+1)*PANELW + rl*AS + c63 + 2) = qq;
        }
    }
    __syncthreads();

    float acc[2][8][4];

    // ---- phase 1: wo GEMM, A resident (panels 0-3), B streamed ----
    #pragma unroll
    for (int mt = 0; mt < 2; mt++)
        #pragma unroll
        for (int nt = 0; nt < 8; nt++)
            #pragma unroll
            for (int q = 0; q < 4; q++) acc[mt][nt][q] = 0.0f;

    for (int kc2 = 0; kc2 < 2; kc2++){
        #pragma unroll
        for (int it = 0; it < 4; it++){
            int idx = it*256 + tid;
            int r = idx >> 3, c8 = (idx & 7) << 3;
            uint32_t so = (uint32_t)((r*AS + c8)*2);
            cp16(sbase + 4*PANEL + so, Bw1 + (size_t)r*DIM + kc2*64 + c8);
            cp16(sbase + 5*PANEL + so, Bw2 + (size_t)r*DIM + kc2*64 + c8);
        }
        CPCOMMIT();
        CPWAIT0();
        __syncthreads();
        chunk_mma<true>(acc, sbase + (uint32_t)(kc2*2*PANEL) + aoff0, boffB);
        __syncthreads();
    }
    gemm_epilogue(acc, row0, 0, biasW, hres, DIM, (bf16*)0, (bf16*)0, 0,
                  lnw, lnb, red, GF_ACCUM|GF_LN|GF_SMEMOUT, lane, warpM, warpN, smem);
    __syncthreads();

    // ---- phase 2: w1 from smem, 4 N-blocks ----
    for (int nb = 0; nb < 4; nb++){
        int cofs = nb*128;
        #pragma unroll
        for (int mt = 0; mt < 2; mt++)
            #pragma unroll
            for (int nt = 0; nt < 8; nt++)
                #pragma unroll
                for (int q = 0; q < 4; q++) acc[mt][nt][q] = 0.0f;

        for (int kc2 = 0; kc2 < 2; kc2++){
            #pragma unroll
            for (int it = 0; it < 4; it++){
                int idx = it*256 + tid;
                int r = idx >> 3, c8 = (idx & 7) << 3;
                uint32_t so = (uint32_t)((r*AS + c8)*2);
                cp16(sbase + 4*PANEL + so, B21 + (size_t)(cofs+r)*DIM + kc2*64 + c8);
                cp16(sbase + 5*PANEL + so, B22 + (size_t)(cofs+r)*DIM + kc2*64 + c8);
            }
            CPCOMMIT();
            CPWAIT0();
            __syncthreads();
            chunk_mma<true>(acc, sbase + (uint32_t)(kc2*2*PANEL) + aoff0, boffB);
            __syncthreads();
        }
        gemm_epilogue(acc, row0, cofs, bias2, (float*)0, 0, O2b, (bf16*)0, ldo2,
                      (float*)0, (float*)0, red, flags2, lane, warpM, warpN, smem);
        __syncthreads();
    }
}

// ---------------- launch ----------------
extern "C" void kernel_launch(void* const* d_in, const int* in_sizes, int n_in,
                              void* d_out, int out_size){
    const float* x    = (const float*)d_in[0];
    const int*   li   = (const int*)  d_in[1];
    const float* ob   = (const float*)d_in[2];
    const float* dw   = (const float*)d_in[3];
    const float* db   = (const float*)d_in[4];
    const float* ln1w = (const float*)d_in[5];
    const float* ln1b = (const float*)d_in[6];
    const float* wqkv = (const float*)d_in[7];
    const float* bqkv = (const float*)d_in[8];
    const float* wo   = (const float*)d_in[9];
    const float* bo   = (const float*)d_in[10];
    const float* ln2w = (const float*)d_in[11];
    const float* ln2b = (const float*)d_in[12];
    const float* w1   = (const float*)d_in[13];
    const float* b1   = (const float*)d_in[14];
    const float* w2   = (const float*)d_in[15];
    const float* b2   = (const float*)d_in[16];
    const float* pw   = (const float*)d_in[17];
    const float* pb   = (const float*)d_in[18];
    int n = in_sizes[0] / DIM;

    bf16 *a1, *a2, *h1a, *fa1, *fa2, *qkvb;
    bf16 *wqT1, *wqT2, *woT1, *woT2, *w1T1, *w1T2, *w2T1, *w2T2, *pT1, *pT2;
    float *h;
    cudaGetSymbolAddress((void**)&a1,  g_a1);  cudaGetSymbolAddress((void**)&a2,  g_a2);
    cudaGetSymbolAddress((void**)&h1a, g_h1a);
    cudaGetSymbolAddress((void**)&fa1, g_fa1); cudaGetSymbolAddress((void**)&fa2, g_fa2);
    cudaGetSymbolAddress((void**)&qkvb, g_qkvb);
    cudaGetSymbolAddress((void**)&wqT1, g_wqkvT1); cudaGetSymbolAddress((void**)&wqT2, g_wqkvT2);
    cudaGetSymbolAddress((void**)&woT1, g_woT1);   cudaGetSymbolAddress((void**)&woT2, g_woT2);
    cudaGetSymbolAddress((void**)&w1T1, g_w1T1);   cudaGetSymbolAddress((void**)&w1T2, g_w1T2);
    cudaGetSymbolAddress((void**)&w2T1, g_w2T1);   cudaGetSymbolAddress((void**)&w2T2, g_w2T2);
    cudaGetSymbolAddress((void**)&pT1, g_pT1);     cudaGetSymbolAddress((void**)&pT2, g_pT2);
    cudaGetSymbolAddress((void**)&h, g_h);

    const int SMEM_ARES = 6*PANEL + 2048;   // 112640
    const int SMEM_STRM = 4*PANEL + 2048;   // 75776
    cudaFuncSetAttribute(k_gemm<true,true>,   cudaFuncAttributeMaxDynamicSharedMemorySize, SMEM_ARES);
    cudaFuncSetAttribute(k_gemm<false,true>,  cudaFuncAttributeMaxDynamicSharedMemorySize, SMEM_STRM);
    cudaFuncSetAttribute(k_gemm<false,false>, cudaFuncAttributeMaxDynamicSharedMemorySize, SMEM_STRM);
    cudaFuncSetAttribute(k_fused<512,false,3>, cudaFuncAttributeMaxDynamicSharedMemorySize, SMEM_ARES);
    cudaFuncSetAttribute(k_afused, cudaFuncAttributeMaxDynamicSharedMemorySize, SMEM_ARES);

    // setup
    k_zero<<<(BALL+255)/256, 256>>>();
    k_scatter<<<(n+255)/256, 256>>>(li, n);
    k_bg<<<2, 256>>>(ob, dw, db);
    k_select<<<(BALL+255)/256, 256>>>();
    k_assemble<<<(NROW*DIM+255)/256, 256>>>(x);

    // weight transpose+split
    k_tsplit<<<dim3(64, DEPTH), 256>>>(wqkv, wqT1, wqT2, DIM, 3*DIM);
    k_tsplit<<<dim3(32, DEPTH), 256>>>(wo,   woT1, woT2, DIM, DIM);
    k_tsplit<<<dim3(64, DEPTH), 256>>>(w1,   w1T1, w1T2, DIM, HID);
    k_tsplit<<<dim3(64, DEPTH), 256>>>(w2,   w2T1, w2T2, HID, DIM);
    k_tsplit<<<dim3(256, 1),    256>>>(pw,   pT1,  pT2,  HID, CLV);

    // layer-0 LN + qkv (bf16 QKV out)
    k_ln_split<<<NROW/8, 256>>>(ln1w, ln1b);
    const int MB = NROW/128;   // 720
    k_gemm<true,true><<<MB, 256, SMEM_ARES>>>(a1, a2, DIM,
        wqT1, wqT2, bqkv, (float*)0, 0, qkvb, (bf16*)0, 3*DIM,
        (float*)0, (float*)0, DIM, 3, GF_B16);

    for (int L = 0; L < DEPTH; L++){
        // fused: attention + wo + residual + ln2 -> smem -> w1 (gelu, bf16 out)
        k_afused<<<MB, 256, SMEM_ARES>>>(qkvb,
            woT1 + (size_t)L*DIM*DIM, woT2 + (size_t)L*DIM*DIM,
            bo + L*DIM, h, ln2w + L*DIM, ln2b + L*DIM,
            w1T1 + (size_t)L*HID*DIM, w1T2 + (size_t)L*HID*DIM,
            b1 + L*HID, h1a, HID, GF_GELU|GF_B16);
        if (L < DEPTH-1){
            // fused: w2 + residual + ln1(L+1) -> smem -> qkv(L+1) (bf16 out)
            k_fused<512,false,3><<<MB, 256, SMEM_ARES>>>(h1a, (bf16*)0, HID,
                w2T1 + (size_t)L*DIM*HID, w2T2 + (size_t)L*DIM*HID,
                b2 + L*DIM, h, ln1w + (L+1)*DIM, ln1b + (L+1)*DIM,
                wqT1 + (size_t)(L+1)*3*DIM*DIM, wqT2 + (size_t)(L+1)*3*DIM*DIM,
                bqkv + (L+1)*3*DIM, (float*)0, 0, qkvb, 3*DIM, GF_B16);
        } else {
            k_gemm<false,false><<<dim3(MB,1), 256, SMEM_STRM>>>(h1a, (bf16*)0, HID,
                w2T1 + (size_t)L*DIM*HID, w2T2 + (size_t)L*DIM*HID,
                b2 + L*DIM, h, DIM, (bf16*)0, (bf16*)0, 0,
                (float*)0, (float*)0, HID, 1, GF_ACCUM);
        }
    }

    k_split_feat<<<(BALL*HID+255)/256, 256>>>();
    k_gemm<false,true><<<dim3(BALL/128, CLV/128), 256, SMEM_STRM>>>(fa1, fa2, HID,
        pT1, pT2, pb, (float*)d_out, CLV, (bf16*)0, (bf16*)0, 0,
        (float*)0, (float*)0, HID, 1, GF_MASK);
}